// round 8
// baseline (speedup 1.0000x reference)
#include <cuda_runtime.h>
#include <math.h>
#include <cstdint>

// Problem constants
#define NBLK 512
#define BQ   32
#define HH   16
#define DD   576
#define DD4  144
#define DVV  512
#define BSS  128
#define QSCALE 0.07216878364870322f  // 192^-0.5

typedef unsigned long long ull;

// Scratch (device globals — no allocation allowed)
__device__ float g_oacc[NBLK * HH * DVV];
__device__ float g_bm[NBLK * HH];
__device__ float g_bs[NBLK * HH];

// ---------------- helpers ----------------
__device__ __forceinline__ uint32_t smem_u32(const void* p) {
    uint32_t a;
    asm("{ .reg .u64 t; cvta.to.shared.u64 t, %1; cvt.u32.u64 %0, t; }" : "=r"(a) : "l"(p));
    return a;
}
__device__ __forceinline__ void cp16(uint32_t dst, const void* src) {
    asm volatile("cp.async.cg.shared.global [%0], [%1], 16;" :: "r"(dst), "l"(src));
}
#define CP_COMMIT() asm volatile("cp.async.commit_group;" ::: "memory")
#define CP_WAIT(n)  asm volatile("cp.async.wait_group %0;" :: "n"(n) : "memory")

__device__ __forceinline__ void fma2(ull& d, ull a, ull b) {
    asm("fma.rn.f32x2 %0, %1, %2, %0;" : "+l"(d) : "l"(a), "l"(b));
}
__device__ __forceinline__ float lo_f(ull v) { return __uint_as_float((unsigned)v); }
__device__ __forceinline__ float hi_f(ull v) { return __uint_as_float((unsigned)(v >> 32)); }
__device__ __forceinline__ ull dup2(float v) {
    unsigned u = __float_as_uint(v);
    return ((ull)u << 32) | u;
}

// ---------------- SMEM layout (bytes) ----------------
// tiles  : 3 x (8 rows x 145 float4) = 3 x 18560        [0, 55680)
// q      : 16 rows x 145 float4 = 37120                 [55680, 92800)
// parts  : 128 cells x 9 floats = 4608                  [92800, 97408)
// sc     : 16 x 9 floats = 576                          [97408, 97984)
// pp     : 16 x 9 floats = 576                          [97984, 98560)
// Mx/Lx/rr : 3 x 16 floats                              [98560, 98752)
// bb     : 128 floats                                   [98752, 99264)
#define TSTR  145
#define TBUF  18560
#define QOFF  55680
#define PARTO 92800
#define SCOFF 97408
#define PPOFF 97984
#define MOFF  98560
#define LOFF  98624
#define RROFF 98688
#define BBOFF 98752
#define SMEM_BYTES 99264

__global__ __launch_bounds__(128, 2) void mla_fused_kernel(
    const float* __restrict__ query,
    const float* __restrict__ key_cache,
    const float* __restrict__ block_bias,
    const int* __restrict__ block_list,
    const int* __restrict__ block_groups)
{
    extern __shared__ char smem[];
    const uint32_t sbase = smem_u32(smem);
    const int t = threadIdx.x;
    const int n = blockIdx.x;
    const int b = block_groups[n];
    const float4* kvb4 = (const float4*)(key_cache + (long)block_list[n] * (BSS * DD));
    const float4* q4 = (const float4*)query;

    const float4* qs4 = (const float4*)(smem + QOFF);
    float* parts = (float*)(smem + PARTO);
    float* sc    = (float*)(smem + SCOFF);
    float* pp    = (float*)(smem + PPOFF);
    float* Mx    = (float*)(smem + MOFF);
    float* Lx    = (float*)(smem + LOFF);
    float* rr    = (float*)(smem + RROFF);
    float* bb    = (float*)(smem + BBOFF);

    // init running stats + bias preload (before first sync)
    if (t < 16) { Mx[t] = -3e38f; Lx[t] = 0.f; }
    bb[t] = block_bias[n * BSS + t];

    // ---- issue Q (16 x 144 f4 -> stride-145 rows)
    {
        #pragma unroll
        for (int j = 0; j < 18; j++) {
            int idx = t + j * 128;
            int row = idx / 144, col = idx - row * 144;
            cp16(sbase + QOFF + (unsigned)(row * TSTR + col) * 16,
                 q4 + (long)(b * HH + row) * DD4 + col);
        }
        CP_COMMIT();
    }
    // ---- tile loader: 8 rows x 144 f4 into buffer tl%3
    auto issueT = [&](int tl) {
        uint32_t tb = sbase + (unsigned)(tl % 3) * TBUF;
        #pragma unroll
        for (int j = 0; j < 9; j++) {
            int idx = t + j * 128;
            int row = idx / 144, col = idx - row * 144;
            cp16(tb + (unsigned)(row * TSTR + col) * 16,
                 kvb4 + (long)(tl * 8 + row) * DD4 + col);
        }
        CP_COMMIT();
    };
    issueT(0);
    issueT(1);

    // thread mappings
    const int g  = t >> 4;        // d-group 0..7 (72 d-floats = 18 f4 each)
    const int u  = t & 15;
    const int hq = u & 3;         // score h-base: h = hq + 4i
    const int sp = u >> 2;        // score s-pair: s = 2*sp + {0,1}
    const int hb = t & 3;         // PV h-base: h = hb + 4i
    const int vb = t >> 2;        // PV f4 column base: col = vb + 32*cc

    // o accumulators: 4 h x 16 v (8 f32x2)
    ull o2[4][8];
    #pragma unroll
    for (int i = 0; i < 4; i++)
        #pragma unroll
        for (int p = 0; p < 8; p++) o2[i][p] = 0ull;

    for (int tl = 0; tl < 16; tl++) {
        if (tl < 15) { CP_WAIT(1); } else { CP_WAIT(0); }
        __syncthreads();                     // tile tl ready; buffer (tl+2)%3 free
        if (tl + 2 < 16) issueT(tl + 2);

        const float4* kt = (const float4*)(smem + (tl % 3) * TBUF);

        // ---- QK partial scores: cells (hq+4i, 2sp+sA), d-range [g*18, g*18+18) f4
        {
            ull acc[4][2];
            #pragma unroll
            for (int i = 0; i < 4; i++) { acc[i][0] = 0ull; acc[i][1] = 0ull; }
            const int kbase = g * 18;
            #pragma unroll
            for (int k4 = 0; k4 < 18; k4++) {
                int kk = kbase + k4;
                ulonglong2 k0 = *(const ulonglong2*)&kt[(2 * sp) * TSTR + kk];
                ulonglong2 k1 = *(const ulonglong2*)&kt[(2 * sp + 1) * TSTR + kk];
                #pragma unroll
                for (int i = 0; i < 4; i++) {
                    ulonglong2 qq = *(const ulonglong2*)&qs4[(hq + 4 * i) * TSTR + kk];
                    fma2(acc[i][0], qq.x, k0.x);
                    fma2(acc[i][0], qq.y, k0.y);
                    fma2(acc[i][1], qq.x, k1.x);
                    fma2(acc[i][1], qq.y, k1.y);
                }
            }
            #pragma unroll
            for (int i = 0; i < 4; i++)
                #pragma unroll
                for (int sA = 0; sA < 2; sA++) {
                    int cell = (hq + 4 * i) * 8 + 2 * sp + sA;
                    parts[cell * 9 + g] = lo_f(acc[i][sA]) + hi_f(acc[i][sA]);
                }
        }
        __syncthreads();

        // ---- reduce partials -> scores (thread t owns cell t)
        {
            float ssum = 0.f;
            #pragma unroll
            for (int gg = 0; gg < 8; gg++) ssum += parts[t * 9 + gg];
            int h = t >> 3, s = t & 7;
            sc[h * 9 + s] = ssum * QSCALE + bb[tl * 8 + s];
        }
        __syncwarp();    // sc row h written/read within the same warp

        // ---- online softmax update
        {
            int h = t >> 3, s = t & 7;
            float tm = sc[h * 9 + 0];
            #pragma unroll
            for (int k = 1; k < 8; k++) tm = fmaxf(tm, sc[h * 9 + k]);
            float Mo = Mx[h];
            float Mn = fmaxf(Mo, tm);
            float r  = __expf(Mo - Mn);
            pp[h * 9 + s] = __expf(sc[h * 9 + s] - Mn);
            rr[h] = r;        // all 8 lanes of h write identical values
            Mx[h] = Mn;
        }
        __syncthreads();

        // ---- L update (one thread per h) runs alongside PV
        if (t < 16) {
            float s8 = 0.f;
            #pragma unroll
            for (int k = 0; k < 8; k++) s8 += pp[t * 9 + k];
            Lx[t] = Lx[t] * rr[t] + s8;
        }

        // ---- rescale o, then PV accumulate over this tile's 8 s-rows
        #pragma unroll
        for (int i = 0; i < 4; i++) {
            ull rd = dup2(rr[hb + 4 * i]);
            #pragma unroll
            for (int p = 0; p < 8; p++) {
                ull tmp = 0ull;
                fma2(tmp, o2[i][p], rd);
                o2[i][p] = tmp;
            }
        }
        #pragma unroll
        for (int s = 0; s < 8; s++) {
            ull pd[4];
            #pragma unroll
            for (int i = 0; i < 4; i++)
                pd[i] = dup2(pp[(hb + 4 * i) * 9 + s]);
            #pragma unroll
            for (int cc = 0; cc < 4; cc++) {
                ulonglong2 vv = *(const ulonglong2*)&kt[s * TSTR + vb + cc * 32];
                #pragma unroll
                for (int i = 0; i < 4; i++) {
                    fma2(o2[i][2 * cc],     pd[i], vv.x);
                    fma2(o2[i][2 * cc + 1], pd[i], vv.y);
                }
            }
        }
    }

    __syncthreads();
    // ---- epilogue: store partial o, block max/sum
    if (t < 16) {
        g_bm[n * HH + t] = Mx[t];
        g_bs[n * HH + t] = Lx[t];
    }
    #pragma unroll
    for (int i = 0; i < 4; i++) {
        int h = hb + 4 * i;
        ulonglong2* dst = (ulonglong2*)(g_oacc + ((long)(n * HH + h)) * DVV);
        #pragma unroll
        for (int cc = 0; cc < 4; cc++) {
            ulonglong2 v; v.x = o2[i][2 * cc]; v.y = o2[i][2 * cc + 1];
            dst[vb + cc * 32] = v;
        }
    }
}

// ---------------- combine: group b owns blocks b*16..b*16+15 ----------------
__global__ __launch_bounds__(512) void mla_combine_kernel(float* __restrict__ out)
{
    const int b = blockIdx.x, h = blockIdx.y, t = threadIdx.x;
    __shared__ float w[16];

    if (t < 16) {
        float m = g_bm[(b * 16 + t) * HH + h];
        float gmax = m;
        #pragma unroll
        for (int o = 8; o >= 1; o >>= 1)
            gmax = fmaxf(gmax, __shfl_xor_sync(0xffffu, gmax, o, 16));
        float e = __expf(m - gmax);
        float gsum = g_bs[(b * 16 + t) * HH + h] * e;
        #pragma unroll
        for (int o = 8; o >= 1; o >>= 1)
            gsum += __shfl_xor_sync(0xffffu, gsum, o, 16);
        w[t] = e / gsum;
    }
    __syncthreads();

    float v[16];
    #pragma unroll
    for (int j = 0; j < 16; j++)
        v[j] = g_oacc[((long)((b * 16 + j) * HH + h)) * DVV + t];

    float acc = 0.f;
    #pragma unroll
    for (int j = 0; j < 16; j++)
        acc += w[j] * v[j];
    out[((long)(b * HH + h)) * DVV + t] = acc;
}

// -----------------------------------------------------------------------------
extern "C" void kernel_launch(void* const* d_in, const int* in_sizes, int n_in,
                              void* d_out, int out_size)
{
    const float* query        = (const float*)d_in[0];
    const float* key_cache    = (const float*)d_in[1];
    const float* block_bias   = (const float*)d_in[3];
    const int*   block_list   = (const int*)d_in[4];
    const int*   block_groups = (const int*)d_in[5];
    float* out = (float*)d_out;

    cudaFuncSetAttribute(mla_fused_kernel,
                         cudaFuncAttributeMaxDynamicSharedMemorySize, SMEM_BYTES);

    mla_fused_kernel<<<NBLK, 128, SMEM_BYTES>>>(
        query, key_cache, block_bias, block_list, block_groups);
    mla_combine_kernel<<<dim3(BQ, HH), 512>>>(out);
}